// round 11
// baseline (speedup 1.0000x reference)
#include <cuda_runtime.h>
#include <cuda_fp16.h>
#include <math.h>
#include <stdint.h>

// Problem constants
constexpr int C_DIM   = 2048;
constexpr int NH      = 16;
constexpr int HD      = 128;
constexpr int SEQ     = 512;
constexpr int NB      = 16;
constexpr int MROWS   = NB * SEQ;        // 8192
constexpr int QKV_N   = 3 * C_DIM;       // 6144

// Scratch (static device globals — no runtime allocation)
__device__ __half g_xh    [(long long)MROWS * C_DIM];   // 32 MiB
__device__ __half g_qkvh  [(long long)MROWS * QKV_N];   // 96 MiB
__device__ __half g_yh    [(long long)MROWS * C_DIM];   // 32 MiB
__device__ __half g_WqkvTh[(long long)QKV_N * C_DIM];   // 24 MiB
__device__ __half g_WoutTh[(long long)C_DIM * C_DIM];   //  8 MiB

// ---------------------------------------------------------------------------
// helpers
// ---------------------------------------------------------------------------
__device__ __forceinline__ uint32_t smem_u32(const void* p) {
    return (uint32_t)__cvta_generic_to_shared(p);
}
__device__ __forceinline__ void cp_async16(uint32_t dst, const void* src) {
    asm volatile("cp.async.cg.shared.global [%0], [%1], 16;\n"
                 :: "r"(dst), "l"(src) : "memory");
}
__device__ __forceinline__ void cp_commit() {
    asm volatile("cp.async.commit_group;\n" ::: "memory");
}
template <int N>
__device__ __forceinline__ void cp_wait_group() {
    asm volatile("cp.async.wait_group %0;\n" :: "n"(N) : "memory");
}
__device__ __forceinline__ void mma_f16(float* c, const uint32_t* a, const uint32_t* b) {
    asm volatile(
        "mma.sync.aligned.m16n8k16.row.col.f32.f16.f16.f32 "
        "{%0,%1,%2,%3}, {%4,%5,%6,%7}, {%8,%9}, {%0,%1,%2,%3};"
        : "+f"(c[0]), "+f"(c[1]), "+f"(c[2]), "+f"(c[3])
        : "r"(a[0]), "r"(a[1]), "r"(a[2]), "r"(a[3]), "r"(b[0]), "r"(b[1]));
}
__device__ __forceinline__ void ldsm_x4(uint32_t* r, uint32_t addr) {
    asm volatile("ldmatrix.sync.aligned.m8n8.x4.shared.b16 {%0,%1,%2,%3}, [%4];"
                 : "=r"(r[0]), "=r"(r[1]), "=r"(r[2]), "=r"(r[3]) : "r"(addr));
}
__device__ __forceinline__ void ldsm_x4_t(uint32_t* r, uint32_t addr) {
    asm volatile("ldmatrix.sync.aligned.m8n8.x4.trans.shared.b16 {%0,%1,%2,%3}, [%4];"
                 : "=r"(r[0]), "=r"(r[1]), "=r"(r[2]), "=r"(r[3]) : "r"(addr));
}
__device__ __forceinline__ uint32_t pack_h2(float lo, float hi) {
    __half2 h = __floats2half2_rn(lo, hi);
    return *(uint32_t*)&h;
}

// ---------------------------------------------------------------------------
// fp32 -> fp16 bulk convert
// ---------------------------------------------------------------------------
__global__ __launch_bounds__(256) void f2h_kernel(
    const float* __restrict__ in, __half* __restrict__ out)
{
    int i = (blockIdx.x * 256 + threadIdx.x) * 4;
    float4 v = *(const float4*)(in + i);
    *(__half2*)(out + i)     = __floats2half2_rn(v.x, v.y);
    *(__half2*)(out + i + 2) = __floats2half2_rn(v.z, v.w);
}

// ---------------------------------------------------------------------------
// Tiled transpose + fp16 convert: out[c][r] = (half)in[r][c].
// ---------------------------------------------------------------------------
__global__ __launch_bounds__(256) void transpose_h_kernel(
    const float* __restrict__ in, __half* __restrict__ out, int R, int Ccols)
{
    __shared__ float t[32][33];
    int c0 = blockIdx.x * 32, r0 = blockIdx.y * 32;
    int x = c0 + threadIdx.x;
#pragma unroll
    for (int i = threadIdx.y; i < 32; i += 8)
        t[i][threadIdx.x] = in[(size_t)(r0 + i) * Ccols + x];
    __syncthreads();
    int ox = r0 + threadIdx.x;
#pragma unroll
    for (int i = threadIdx.y; i < 32; i += 8)
        out[(size_t)(c0 + i) * R + ox] = __float2half_rn(t[threadIdx.x][i]);
}

// ---------------------------------------------------------------------------
// RoPE in-place on fp16 qkv (fp32 math)
// ---------------------------------------------------------------------------
__global__ __launch_bounds__(256) void rope_h_kernel(__half* __restrict__ qkv)
{
    int idx = blockIdx.x * blockDim.x + threadIdx.x;
    int d = idx & 7;
    int h = (idx >> 3) & 15;
    int w = (idx >> 7) & 1;
    int m = idx >> 8;
    int t = m & (SEQ - 1);

    size_t base = (size_t)m * QKV_N + w * C_DIM + h * HD;
    float inv = powf(10000.0f, -(float)d * 0.125f);
    float ang = (float)t * inv;
    float s, c;
    sincosf(ang, &s, &c);
    float x1 = __half2float(qkv[base + d]);
    float x2 = __half2float(qkv[base + d + 8]);
    qkv[base + d]     = __float2half_rn(x1 * c - x2 * s);
    qkv[base + d + 8] = __float2half_rn(x2 * c + x1 * s);
}

// ---------------------------------------------------------------------------
// fp16 tensor-core GEMM with ldmatrix:  C[M,N] = A[M,K] @ Bt[N,K]^T
// CTA 128x128, BK=64, 8 warps (2x4), warp tile 64x32, 3-stage cp.async.
// Explicit 2-deep register fragment pipeline: LDSMs of k-step ks+1 issue
// before MMAs of ks, so the tensor pipe never waits on the LDSM burst.
// One __syncthreads per mainloop iter. 2 CTAs/SM.
// ---------------------------------------------------------------------------
constexpr int HG_BM = 128, HG_BN = 128, HG_BK = 64, HG_NST = 3;
constexpr int HG_AP = 72;                    // halves per smem row (64 + 8)
constexpr int HG_AT = 128 * HG_AP;           // 9216 halves (A tile)
constexpr int HG_ST = 2 * HG_AT;             // 18432 halves / stage
constexpr int HG_SMEM_BYTES = HG_NST * HG_ST * 2;   // 110592

template <typename OutT>
__global__ __launch_bounds__(256, 2) void hgemm_kernel(
    const __half* __restrict__ A, const __half* __restrict__ Bt,
    OutT* __restrict__ C, int M, int N, int K)
{
    extern __shared__ __half smh[];
    const uint32_t sb = smem_u32(smh);

    const int tid  = threadIdx.x;
    const int warp = tid >> 5;
    const int lane = tid & 31;
    const int qr   = lane >> 2;
    const int qc   = lane & 3;
    const int m0   = blockIdx.y * HG_BM;
    const int n0   = blockIdx.x * HG_BN;
    const int wm   = (warp >> 2) * 64;
    const int wn   = (warp & 3) * 32;

    // ldmatrix lane offsets (in halves)
    const uint32_t aoff = (uint32_t)(((lane & 7) + ((lane >> 3) & 1) * 8) * HG_AP + (lane >> 4) * 8);
    const uint32_t boff = (uint32_t)(((lane & 7) + (lane >> 4) * 8) * HG_AP + ((lane >> 3) & 1) * 8);

    float acc[4][4][4];
#pragma unroll
    for (int mi = 0; mi < 4; ++mi)
#pragma unroll
        for (int ni = 0; ni < 4; ++ni)
#pragma unroll
            for (int r = 0; r < 4; ++r) acc[mi][ni][r] = 0.f;

    const int NITER = K / HG_BK;

    auto load_stage = [&](int ki) {
        const int k0  = ki * HG_BK;
        const int buf = ki % HG_NST;
        const uint32_t sa  = sb + (uint32_t)buf * HG_ST * 2;
        const uint32_t sbb = sa + HG_AT * 2;
#pragma unroll
        for (int it = 0; it < 4; ++it) {
            int idx = it * 256 + tid;
            int r = idx >> 3, c8 = idx & 7;
            cp_async16(sa + (uint32_t)(r * HG_AP + c8 * 8) * 2,
                       A + (size_t)(m0 + r) * K + k0 + c8 * 8);
        }
#pragma unroll
        for (int it = 0; it < 4; ++it) {
            int idx = it * 256 + tid;
            int r = idx >> 3, c8 = idx & 7;
            cp_async16(sbb + (uint32_t)(r * HG_AP + c8 * 8) * 2,
                       Bt + (size_t)(n0 + r) * K + k0 + c8 * 8);
        }
    };

    load_stage(0); cp_commit();
    load_stage(1); cp_commit();

    for (int i = 0; i < NITER; ++i) {
        cp_wait_group<1>();
        __syncthreads();

        const uint32_t sa  = sb + (uint32_t)(i % HG_NST) * HG_ST * 2;
        const uint32_t sbb = sa + HG_AT * 2;

        // fragment double buffer
        uint32_t af[2][4][4], bf[2][2][4];

        auto ld_frags = [&](int ks, uint32_t (*afd)[4], uint32_t (*bfd)[4]) {
#pragma unroll
            for (int mi = 0; mi < 4; ++mi)
                ldsm_x4(afd[mi], sa + (uint32_t)((wm + mi * 16) * HG_AP + ks * 16) * 2 + aoff * 2);
#pragma unroll
            for (int np = 0; np < 2; ++np)
                ldsm_x4(bfd[np], sbb + (uint32_t)((wn + np * 16) * HG_AP + ks * 16) * 2 + boff * 2);
        };

        // preload ks=0 fragments, then issue next stage's cp.async
        ld_frags(0, af[0], bf[0]);

        if (i + 2 < NITER) load_stage(i + 2);
        cp_commit();

#pragma unroll
        for (int ks = 0; ks < 4; ++ks) {
            const int cur = ks & 1;
            if (ks < 3) ld_frags(ks + 1, af[cur ^ 1], bf[cur ^ 1]);
#pragma unroll
            for (int mi = 0; mi < 4; ++mi)
#pragma unroll
                for (int np = 0; np < 2; ++np) {
                    mma_f16(acc[mi][np * 2],     af[cur][mi], &bf[cur][np][0]);
                    mma_f16(acc[mi][np * 2 + 1], af[cur][mi], &bf[cur][np][2]);
                }
        }
        // no trailing __syncthreads — next iter's top barrier protects reuse.
    }

    // epilogue
#pragma unroll
    for (int mi = 0; mi < 4; ++mi) {
#pragma unroll
        for (int ni = 0; ni < 4; ++ni) {
            int row = m0 + wm + mi * 16 + qr;
            int col = n0 + wn + ni * 8 + 2 * qc;
            if constexpr (sizeof(OutT) == 2) {
                *(__half2*)&C[(size_t)row * N + col] =
                    __floats2half2_rn(acc[mi][ni][0], acc[mi][ni][1]);
                *(__half2*)&C[(size_t)(row + 8) * N + col] =
                    __floats2half2_rn(acc[mi][ni][2], acc[mi][ni][3]);
            } else {
                *(float2*)&C[(size_t)row * N + col] =
                    make_float2(acc[mi][ni][0], acc[mi][ni][1]);
                *(float2*)&C[(size_t)(row + 8) * N + col] =
                    make_float2(acc[mi][ni][2], acc[mi][ni][3]);
            }
        }
    }
}

// ---------------------------------------------------------------------------
// fp16 flash attention (causal) with ldmatrix + register-resident P.
// CTA: 128 q-rows of one (b,h); 8 warps x 16 q-rows.
// K and V both row-major [64][136] in smem, double-buffered.
// ---------------------------------------------------------------------------
constexpr int AH_KP  = 136;                       // pitch (halves)
constexpr int AH_K0  = 0;
constexpr int AH_K1  = AH_K0 + 64 * AH_KP;        // 8704
constexpr int AH_V0  = AH_K1 + 64 * AH_KP;        // 17408
constexpr int AH_V1  = AH_V0 + 64 * AH_KP;        // 26112
constexpr int AH_SMEM_HALVES = AH_V1 + 64 * AH_KP;   // 34816
constexpr int AH_SMEM_BYTES  = AH_SMEM_HALVES * 2;   // 69632

__global__ __launch_bounds__(256, 1) void attn_kernel(
    const __half* __restrict__ qkv, __half* __restrict__ y)
{
    extern __shared__ __half smh[];
    const uint32_t sb = smem_u32(smh);
    const int tid  = threadIdx.x;
    const int warp = tid >> 5;
    const int lane = tid & 31;
    const int qr   = lane >> 2;
    const int qc   = lane & 3;
    const int qt   = blockIdx.x;            // 128-row q tile, 0..3
    const int bh   = blockIdx.y;
    const int b = bh >> 4, h = bh & 15;

    const __half* baseQ = qkv + (size_t)b * SEQ * QKV_N + h * HD;
    const __half* baseK = baseQ + C_DIM;
    const __half* baseV = baseQ + 2 * C_DIM;
    const int q0 = qt * 128;

    // ldmatrix lane offsets (halves), pitch AH_KP
    const uint32_t aoff = (uint32_t)(((lane & 7) + ((lane >> 3) & 1) * 8) * AH_KP + (lane >> 4) * 8);
    const uint32_t koff = (uint32_t)(((lane & 7) + (lane >> 4) * 8) * AH_KP + ((lane >> 3) & 1) * 8);
    const uint32_t voff = aoff;   // trans V uses the A-style address pattern

    // ---- stage Q (128 x 128 halves) into V0+V1 region
#pragma unroll
    for (int it = 0; it < 8; ++it) {
        int idx = it * 256 + tid;
        int r = idx >> 4, c8 = idx & 15;
        cp_async16(sb + (uint32_t)(AH_V0 + r * AH_KP + c8 * 8) * 2,
                   baseQ + (size_t)(q0 + r) * QKV_N + c8 * 8);
    }
    cp_commit(); cp_wait_group<0>(); __syncthreads();

    // Q fragments via ldmatrix (8 k-steps of 16 over d)
    uint32_t qf[8][4];
    {
        const uint32_t qbase = sb + (uint32_t)(AH_V0 + warp * 16 * AH_KP) * 2 + aoff * 2;
#pragma unroll
        for (int ks = 0; ks < 8; ++ks)
            ldsm_x4(qf[ks], qbase + (uint32_t)(ks * 16) * 2);
    }
    __syncthreads();

    float O[16][4];
#pragma unroll
    for (int dt = 0; dt < 16; ++dt)
#pragma unroll
        for (int r = 0; r < 4; ++r) O[dt][r] = 0.f;
    float m[2] = {-1e30f, -1e30f}, l[2] = {0.f, 0.f};

    const int nkt = 2 * qt + 2;

    auto load_kv = [&](int kt) {
        int buf = kt & 1;
        int t0  = kt * 64;
        const uint32_t kb = sb + (uint32_t)(buf ? AH_K1 : AH_K0) * 2;
        const uint32_t vb = sb + (uint32_t)(buf ? AH_V1 : AH_V0) * 2;
#pragma unroll
        for (int it = 0; it < 4; ++it) {
            int idx = it * 256 + tid;
            int r = idx >> 4, c8 = idx & 15;
            cp_async16(kb + (uint32_t)(r * AH_KP + c8 * 8) * 2,
                       baseK + (size_t)(t0 + r) * QKV_N + c8 * 8);
        }
#pragma unroll
        for (int it = 0; it < 4; ++it) {
            int idx = it * 256 + tid;
            int r = idx >> 4, c8 = idx & 15;
            cp_async16(vb + (uint32_t)(r * AH_KP + c8 * 8) * 2,
                       baseV + (size_t)(t0 + r) * QKV_N + c8 * 8);
        }
    };

    load_kv(0); cp_commit();
    load_kv(1); cp_commit();

    const int qbase_w = q0 + warp * 16;
    const float scl = 0.08838834764831845f;   // 1/sqrt(128)

    for (int kt = 0; kt < nkt; ++kt) {
        cp_wait_group<1>();
        __syncthreads();
        const uint32_t kb = sb + (uint32_t)((kt & 1) ? AH_K1 : AH_K0) * 2;
        const uint32_t vb = sb + (uint32_t)((kt & 1) ? AH_V1 : AH_V0) * 2;

        // ---- S = Q @ K^T  (warp: 16 x 64)
        float s[8][4];
#pragma unroll
        for (int ni = 0; ni < 8; ++ni)
#pragma unroll
            for (int r = 0; r < 4; ++r) s[ni][r] = 0.f;

#pragma unroll
        for (int ks = 0; ks < 8; ++ks) {
#pragma unroll
            for (int np = 0; np < 4; ++np) {
                uint32_t bf[4];
                ldsm_x4(bf, kb + (uint32_t)(np * 16 * AH_KP + ks * 16) * 2 + koff * 2);
                mma_f16(s[np * 2],     qf[ks], &bf[0]);
                mma_f16(s[np * 2 + 1], qf[ks], &bf[2]);
            }
        }

        // ---- scale + causal mask + online softmax (P stays in registers)
        const bool domask = (kt * 64 + 63 > qbase_w);
#pragma unroll
        for (int r = 0; r < 2; ++r) {
            int qg = qbase_w + qr + 8 * r;
            float mx = -1e30f;
#pragma unroll
            for (int ni = 0; ni < 8; ++ni) {
#pragma unroll
                for (int v = 0; v < 2; ++v) {
                    float val = s[ni][r * 2 + v] * scl;
                    if (domask) {
                        int kg = kt * 64 + ni * 8 + 2 * qc + v;
                        if (kg > qg) val = -1e30f;
                    }
                    s[ni][r * 2 + v] = val;
                    mx = fmaxf(mx, val);
                }
            }
            mx = fmaxf(mx, __shfl_xor_sync(0xffffffffu, mx, 1));
            mx = fmaxf(mx, __shfl_xor_sync(0xffffffffu, mx, 2));
            float mnew  = fmaxf(m[r], mx);
            float alpha = __expf(m[r] - mnew);
            float sum = 0.f;
#pragma unroll
            for (int ni = 0; ni < 8; ++ni) {
                float p0 = __expf(s[ni][r * 2]     - mnew);
                float p1 = __expf(s[ni][r * 2 + 1] - mnew);
                sum += p0 + p1;
                s[ni][r * 2]     = p0;
                s[ni][r * 2 + 1] = p1;
            }
            sum += __shfl_xor_sync(0xffffffffu, sum, 1);
            sum += __shfl_xor_sync(0xffffffffu, sum, 2);
            l[r] = l[r] * alpha + sum;
            m[r] = mnew;
#pragma unroll
            for (int dt = 0; dt < 16; ++dt) {
                O[dt][r * 2]     *= alpha;
                O[dt][r * 2 + 1] *= alpha;
            }
        }

        // ---- O += P @ V  (P from accumulator frags; V via ldmatrix.trans)
#pragma unroll
        for (int kk = 0; kk < 4; ++kk) {
            uint32_t af[4] = {
                pack_h2(s[2 * kk][0],     s[2 * kk][1]),
                pack_h2(s[2 * kk][2],     s[2 * kk][3]),
                pack_h2(s[2 * kk + 1][0], s[2 * kk + 1][1]),
                pack_h2(s[2 * kk + 1][2], s[2 * kk + 1][3]) };
#pragma unroll
            for (int dp = 0; dp < 8; ++dp) {
                uint32_t bf[4];
                ldsm_x4_t(bf, vb + (uint32_t)(kk * 16 * AH_KP + dp * 16) * 2 + voff * 2);
                mma_f16(O[dp * 2],     af, &bf[0]);
                mma_f16(O[dp * 2 + 1], af, &bf[2]);
            }
        }

        __syncthreads();
        if (kt + 2 < nkt) load_kv(kt + 2);
        cp_commit();
    }

    // ---- finalize, write y (fp16)
#pragma unroll
    for (int r = 0; r < 2; ++r) {
        float inv = 1.0f / l[r];
        int row = qbase_w + qr + 8 * r;
        __half* yp = y + (size_t)(b * SEQ + row) * C_DIM + h * HD;
#pragma unroll
        for (int dt = 0; dt < 16; ++dt)
            *(__half2*)&yp[dt * 8 + 2 * qc] =
                __floats2half2_rn(O[dt][r * 2] * inv, O[dt][r * 2 + 1] * inv);
    }
}

// ---------------------------------------------------------------------------
extern "C" void kernel_launch(void* const* d_in, const int* in_sizes, int n_in,
                              void* d_out, int out_size)
{
    const float* x    = (const float*)d_in[0];
    const float* Wqkv = (const float*)d_in[1];
    const float* Wout = (const float*)d_in[2];
    float* out = (float*)d_out;

    __half *xh, *qkvh, *yh, *wqkvTh, *woutTh;
    cudaGetSymbolAddress((void**)&xh,     g_xh);
    cudaGetSymbolAddress((void**)&qkvh,   g_qkvh);
    cudaGetSymbolAddress((void**)&yh,     g_yh);
    cudaGetSymbolAddress((void**)&wqkvTh, g_WqkvTh);
    cudaGetSymbolAddress((void**)&woutTh, g_WoutTh);

    static bool attr_set = false;
    if (!attr_set) {
        cudaFuncSetAttribute(hgemm_kernel<__half>, cudaFuncAttributeMaxDynamicSharedMemorySize, HG_SMEM_BYTES);
        cudaFuncSetAttribute(hgemm_kernel<float>,  cudaFuncAttributeMaxDynamicSharedMemorySize, HG_SMEM_BYTES);
        cudaFuncSetAttribute(attn_kernel,          cudaFuncAttributeMaxDynamicSharedMemorySize, AH_SMEM_BYTES);
        attr_set = true;
    }

    // 0) convert x -> fp16; transpose+convert weights -> [N,K] fp16
    f2h_kernel<<<(MROWS * C_DIM / 4) / 256, 256>>>(x, xh);
    transpose_h_kernel<<<dim3(QKV_N / 32, C_DIM / 32), dim3(32, 8)>>>(Wqkv, wqkvTh, C_DIM, QKV_N);
    transpose_h_kernel<<<dim3(C_DIM / 32, C_DIM / 32), dim3(32, 8)>>>(Wout, woutTh, C_DIM, C_DIM);

    // 1) qkv = x @ Wqkv  (fp16 MMA, fragment-pipelined mainloop)
    hgemm_kernel<__half><<<dim3(QKV_N / HG_BN, MROWS / HG_BM), 256, HG_SMEM_BYTES>>>(
        xh, wqkvTh, qkvh, MROWS, QKV_N, C_DIM);

    // 2) RoPE in-place on q,k (fp16)
    rope_h_kernel<<<(MROWS * 2 * NH * 8) / 256, 256>>>(qkvh);

    // 3) causal flash attention (fp16 MMA + ldmatrix, register P) -> y fp16
    attn_kernel<<<dim3(SEQ / 128, NB * NH), 256, AH_SMEM_BYTES>>>(qkvh, yh);

    // 4) out = y @ Wout  (fp16 MMA, fragment-pipelined mainloop, fp32 out)
    hgemm_kernel<float><<<dim3(C_DIM / HG_BN, MROWS / HG_BM), 256, HG_SMEM_BYTES>>>(
        yh, woutTh, out, MROWS, C_DIM, C_DIM);
}